// round 1
// baseline (speedup 1.0000x reference)
#include <cuda_runtime.h>
#include <math.h>

#define DIMC 1024
#define NTOK 2048
#define BATCHN 2
#define TTOK (BATCHN*NTOK)   /* 4096 tokens */
#define NHEADS 16
#define HDIM 64
#define DFF 4096

/* ---------------- scratch (no allocations allowed -> device globals) ------ */
__device__ float g_bufA[(size_t)TTOK*DIMC];          /* 16 MB */
__device__ float g_bufB[(size_t)TTOK*DIMC];          /* 16 MB */
__device__ float g_qkv [(size_t)TTOK*3*DIMC];        /* 48 MB (also q/k/v for kernel-attn) */
__device__ float g_ff  [(size_t)TTOK*DFF];           /* 64 MB */
__device__ float g_sc  [(size_t)BATCHN*NHEADS*NTOK*NTOK]; /* 512 MB scores */

/* ---------------- helpers ------------------------------------------------- */
__device__ __forceinline__ float gelu_f(float x) {
    return 0.5f * x * (1.0f + erff(x * 0.7071067811865476f));
}
__device__ __forceinline__ float theta_fn(float x) {
    float sg = 1.0f / (1.0f + __expf(-x));
    float rl = fmaxf(x, 0.0f);
    return 0.5f + 0.2f * sg + 0.15f * tanhf(x) + 0.1f * rl;
}

/* ---------------- generic tiled SGEMM ------------------------------------ */
/* C[z] = alpha * A[z] (MxK) * op(B[z]) + bias ; op = B (KxN, NN) or B^T (NxK, NT)
   batch offset: off = (z/zdiv)*s1 + (z%zdiv)*s2 for each of A,B,C.
   Requires M%64==0, N%64==0, K%16==0, all row pointers 16B aligned. */
template<bool TB, bool GELU>
__global__ void __launch_bounds__(256) gemm_kernel(
    const float* __restrict__ A, const float* __restrict__ B, float* __restrict__ C,
    const float* __restrict__ bias,
    int N, int K, int lda, int ldb, int ldc, int zdiv,
    long long sA1, long long sA2, long long sB1, long long sB2,
    long long sC1, long long sC2, float alpha)
{
    __shared__ float As[16][64];
    __shared__ float Bs[16][64];
    int z  = blockIdx.z;
    int z1 = z / zdiv, z2 = z % zdiv;
    const float* Ab = A + z1 * sA1 + z2 * sA2;
    const float* Bb = B + z1 * sB1 + z2 * sB2;
    float*       Cb = C + z1 * sC1 + z2 * sC2;

    int rowBase = blockIdx.y * 64;
    int colBase = blockIdx.x * 64;
    int tid = threadIdx.x;
    int am  = tid & 63;            /* 0..63  (m for A load / n for B^T load) */
    int ak  = (tid >> 6) << 2;     /* 0,4,8,12 */
    int bn4 = (tid & 15) << 2;     /* NN B load */
    int bk  = tid >> 4;            /* 0..15 */
    int ty4 = (tid >> 4) << 2;
    int tx4 = (tid & 15) << 2;

    float acc[4][4] = {};
    const float* aPtr = Ab + (long long)(rowBase + am) * lda + ak;

    for (int k0 = 0; k0 < K; k0 += 16) {
        float4 av = *(const float4*)(aPtr + k0);
        As[ak+0][am] = av.x; As[ak+1][am] = av.y;
        As[ak+2][am] = av.z; As[ak+3][am] = av.w;
        if (TB) {
            float4 bv = *(const float4*)(Bb + (long long)(colBase + am) * ldb + k0 + ak);
            Bs[ak+0][am] = bv.x; Bs[ak+1][am] = bv.y;
            Bs[ak+2][am] = bv.z; Bs[ak+3][am] = bv.w;
        } else {
            float4 bv = *(const float4*)(Bb + (long long)(k0 + bk) * ldb + colBase + bn4);
            *(float4*)&Bs[bk][bn4] = bv;
        }
        __syncthreads();
        #pragma unroll
        for (int kk = 0; kk < 16; kk++) {
            float4 ra = *(const float4*)&As[kk][ty4];
            float4 rb = *(const float4*)&Bs[kk][tx4];
            acc[0][0] += ra.x*rb.x; acc[0][1] += ra.x*rb.y; acc[0][2] += ra.x*rb.z; acc[0][3] += ra.x*rb.w;
            acc[1][0] += ra.y*rb.x; acc[1][1] += ra.y*rb.y; acc[1][2] += ra.y*rb.z; acc[1][3] += ra.y*rb.w;
            acc[2][0] += ra.z*rb.x; acc[2][1] += ra.z*rb.y; acc[2][2] += ra.z*rb.z; acc[2][3] += ra.z*rb.w;
            acc[3][0] += ra.w*rb.x; acc[3][1] += ra.w*rb.y; acc[3][2] += ra.w*rb.z; acc[3][3] += ra.w*rb.w;
        }
        __syncthreads();
    }

    float4 bvv = make_float4(0.f, 0.f, 0.f, 0.f);
    if (bias) bvv = *(const float4*)(bias + colBase + tx4);
    #pragma unroll
    for (int i = 0; i < 4; i++) {
        float4 o;
        o.x = acc[i][0] * alpha + bvv.x;
        o.y = acc[i][1] * alpha + bvv.y;
        o.z = acc[i][2] * alpha + bvv.z;
        o.w = acc[i][3] * alpha + bvv.w;
        if (GELU) { o.x = gelu_f(o.x); o.y = gelu_f(o.y); o.z = gelu_f(o.z); o.w = gelu_f(o.w); }
        *(float4*)(Cb + (long long)(rowBase + ty4 + i) * ldc + colBase + tx4) = o;
    }
}

/* ---------------- row softmax over 2048 (in place) ------------------------ */
__global__ void __launch_bounds__(256) softmax2048(float* __restrict__ S)
{
    __shared__ float red[8];
    float* row = S + (long long)blockIdx.x * 2048;
    int tid = threadIdx.x;
    float4 v0 = ((float4*)row)[tid];
    float4 v1 = ((float4*)row)[tid + 256];
    float m = fmaxf(fmaxf(fmaxf(v0.x, v0.y), fmaxf(v0.z, v0.w)),
                    fmaxf(fmaxf(v1.x, v1.y), fmaxf(v1.z, v1.w)));
    #pragma unroll
    for (int o = 16; o; o >>= 1) m = fmaxf(m, __shfl_xor_sync(0xffffffffu, m, o));
    if ((tid & 31) == 0) red[tid >> 5] = m;
    __syncthreads();
    m = fmaxf(fmaxf(fmaxf(red[0], red[1]), fmaxf(red[2], red[3])),
              fmaxf(fmaxf(red[4], red[5]), fmaxf(red[6], red[7])));
    v0.x = __expf(v0.x - m); v0.y = __expf(v0.y - m); v0.z = __expf(v0.z - m); v0.w = __expf(v0.w - m);
    v1.x = __expf(v1.x - m); v1.y = __expf(v1.y - m); v1.z = __expf(v1.z - m); v1.w = __expf(v1.w - m);
    float s = v0.x + v0.y + v0.z + v0.w + v1.x + v1.y + v1.z + v1.w;
    #pragma unroll
    for (int o = 16; o; o >>= 1) s += __shfl_xor_sync(0xffffffffu, s, o);
    __syncthreads();
    if ((tid & 31) == 0) red[tid >> 5] = s;
    __syncthreads();
    s = red[0] + red[1] + red[2] + red[3] + red[4] + red[5] + red[6] + red[7];
    float r = 1.0f / s;
    v0.x *= r; v0.y *= r; v0.z *= r; v0.w *= r;
    v1.x *= r; v1.y *= r; v1.z *= r; v1.w *= r;
    ((float4*)row)[tid] = v0;
    ((float4*)row)[tid + 256] = v1;
}

/* ---------------- theta transform + row softmax over 2048 ---------------- */
__global__ void __launch_bounds__(256) theta_softmax2048(float* __restrict__ S)
{
    __shared__ float red[8];
    float* row = S + (long long)blockIdx.x * 2048;
    int tid = threadIdx.x;
    float4 v0 = ((float4*)row)[tid];
    float4 v1 = ((float4*)row)[tid + 256];
    v0.x = theta_fn(v0.x); v0.y = theta_fn(v0.y); v0.z = theta_fn(v0.z); v0.w = theta_fn(v0.w);
    v1.x = theta_fn(v1.x); v1.y = theta_fn(v1.y); v1.z = theta_fn(v1.z); v1.w = theta_fn(v1.w);
    float m = fmaxf(fmaxf(fmaxf(v0.x, v0.y), fmaxf(v0.z, v0.w)),
                    fmaxf(fmaxf(v1.x, v1.y), fmaxf(v1.z, v1.w)));
    #pragma unroll
    for (int o = 16; o; o >>= 1) m = fmaxf(m, __shfl_xor_sync(0xffffffffu, m, o));
    if ((tid & 31) == 0) red[tid >> 5] = m;
    __syncthreads();
    m = fmaxf(fmaxf(fmaxf(red[0], red[1]), fmaxf(red[2], red[3])),
              fmaxf(fmaxf(red[4], red[5]), fmaxf(red[6], red[7])));
    v0.x = __expf(v0.x - m); v0.y = __expf(v0.y - m); v0.z = __expf(v0.z - m); v0.w = __expf(v0.w - m);
    v1.x = __expf(v1.x - m); v1.y = __expf(v1.y - m); v1.z = __expf(v1.z - m); v1.w = __expf(v1.w - m);
    float s = v0.x + v0.y + v0.z + v0.w + v1.x + v1.y + v1.z + v1.w;
    #pragma unroll
    for (int o = 16; o; o >>= 1) s += __shfl_xor_sync(0xffffffffu, s, o);
    __syncthreads();
    if ((tid & 31) == 0) red[tid >> 5] = s;
    __syncthreads();
    s = red[0] + red[1] + red[2] + red[3] + red[4] + red[5] + red[6] + red[7];
    float r = 1.0f / s;
    v0.x *= r; v0.y *= r; v0.z *= r; v0.w *= r;
    v1.x *= r; v1.y *= r; v1.z *= r; v1.w *= r;
    ((float4*)row)[tid] = v0;
    ((float4*)row)[tid + 256] = v1;
}

/* ---------------- LayerNorm over 1024 ------------------------------------ */
__global__ void __launch_bounds__(256) layernorm1024(
    const float* __restrict__ X, const float* __restrict__ g,
    const float* __restrict__ bta, float* __restrict__ Y)
{
    __shared__ float rs[8], rq[8];
    long long base = (long long)blockIdx.x * 1024;
    int tid = threadIdx.x;
    float4 v = *(const float4*)(X + base + tid * 4);
    float s = v.x + v.y + v.z + v.w;
    float q = v.x*v.x + v.y*v.y + v.z*v.z + v.w*v.w;
    #pragma unroll
    for (int o = 16; o; o >>= 1) {
        s += __shfl_xor_sync(0xffffffffu, s, o);
        q += __shfl_xor_sync(0xffffffffu, q, o);
    }
    if ((tid & 31) == 0) { rs[tid >> 5] = s; rq[tid >> 5] = q; }
    __syncthreads();
    s = rs[0] + rs[1] + rs[2] + rs[3] + rs[4] + rs[5] + rs[6] + rs[7];
    q = rq[0] + rq[1] + rq[2] + rq[3] + rq[4] + rq[5] + rq[6] + rq[7];
    float mu  = s * (1.0f / 1024.0f);
    float var = q * (1.0f / 1024.0f) - mu * mu;
    float inv = rsqrtf(var + 1e-5f);
    float4 gg = *(const float4*)(g + tid * 4);
    float4 bb = *(const float4*)(bta + tid * 4);
    float4 o;
    o.x = (v.x - mu) * inv * gg.x + bb.x;
    o.y = (v.y - mu) * inv * gg.y + bb.y;
    o.z = (v.z - mu) * inv * gg.z + bb.z;
    o.w = (v.w - mu) * inv * gg.w + bb.w;
    *(float4*)(Y + base + tid * 4) = o;
}

/* ---------------- residual add ------------------------------------------- */
__global__ void __launch_bounds__(256) add_vec(
    float* __restrict__ out, const float* __restrict__ a, const float* __restrict__ b)
{
    int i = blockIdx.x * 256 + threadIdx.x;
    float4 av = ((const float4*)a)[i];
    float4 bv = ((const float4*)b)[i];
    av.x += bv.x; av.y += bv.y; av.z += bv.z; av.w += bv.w;
    ((float4*)out)[i] = av;
}

/* ---------------- host-side dispatch -------------------------------------- */
static inline void launch_gemm(
    const float* A, const float* B, float* C, const float* bias,
    int M, int N, int K, int lda, int ldb, int ldc,
    int batches, int zdiv,
    long long sA1, long long sA2, long long sB1, long long sB2,
    long long sC1, long long sC2,
    float alpha, bool tb, bool gelu)
{
    dim3 grid(N / 64, M / 64, batches), block(256);
    if (tb)
        gemm_kernel<true,  false><<<grid, block>>>(A, B, C, bias, N, K, lda, ldb, ldc,
                                                   zdiv, sA1, sA2, sB1, sB2, sC1, sC2, alpha);
    else if (gelu)
        gemm_kernel<false, true ><<<grid, block>>>(A, B, C, bias, N, K, lda, ldb, ldc,
                                                   zdiv, sA1, sA2, sB1, sB2, sC1, sC2, alpha);
    else
        gemm_kernel<false, false><<<grid, block>>>(A, B, C, bias, N, K, lda, ldb, ldc,
                                                   zdiv, sA1, sA2, sB1, sB2, sC1, sC2, alpha);
}

extern "C" void kernel_launch(void* const* d_in, const int* in_sizes, int n_in,
                              void* d_out, int out_size)
{
    const float* x     = (const float*)d_in[0];
    const float* ln1_g = (const float*)d_in[1];
    const float* ln1_b = (const float*)d_in[2];
    const float* qkv_w = (const float*)d_in[3];
    const float* qkv_b = (const float*)d_in[4];
    const float* proj_w= (const float*)d_in[5];
    const float* proj_b= (const float*)d_in[6];
    const float* kq_w  = (const float*)d_in[7];
    const float* kq_b  = (const float*)d_in[8];
    const float* kk_w  = (const float*)d_in[9];
    const float* kk_b  = (const float*)d_in[10];
    const float* kv_w  = (const float*)d_in[11];
    const float* kv_b  = (const float*)d_in[12];
    const float* ko_w  = (const float*)d_in[13];
    const float* ko_b  = (const float*)d_in[14];
    const float* ln2_g = (const float*)d_in[15];
    const float* ln2_b = (const float*)d_in[16];
    const float* fc1_w = (const float*)d_in[17];
    const float* fc1_b = (const float*)d_in[18];
    const float* fc2_w = (const float*)d_in[19];
    const float* fc2_b = (const float*)d_in[20];
    float* out = (float*)d_out;

    float *bufA, *bufB, *qkv, *ff, *sc;
    cudaGetSymbolAddress((void**)&bufA, g_bufA);
    cudaGetSymbolAddress((void**)&bufB, g_bufB);
    cudaGetSymbolAddress((void**)&qkv,  g_qkv);
    cudaGetSymbolAddress((void**)&ff,   g_ff);
    cudaGetSymbolAddress((void**)&sc,   g_sc);

    const long long NN   = (long long)NTOK * NTOK;
    const long long TC   = (long long)NTOK * DIMC;   /* per-batch token*dim */
    const int nElemBlks  = (TTOK * DIMC) / (4 * 256);

    /* ---- sublayer 1: MHA ---- */
    layernorm1024<<<TTOK, 256>>>(x, ln1_g, ln1_b, bufA);

    /* qkv = ln1 @ qkv_w + b  -> [T, 3072] */
    launch_gemm(bufA, qkv_w, qkv, qkv_b, TTOK, 3*DIMC, DIMC,
                DIMC, 3*DIMC, 3*DIMC, 1, 1, 0,0, 0,0, 0,0, 1.0f, false, false);

    /* per-head scores = q @ k^T * scale ; z = b*16+h */
    launch_gemm(qkv /*q*/, qkv + DIMC /*k*/, sc, nullptr,
                NTOK, NTOK, HDIM, 3*DIMC, 3*DIMC, NTOK,
                BATCHN*NHEADS, NHEADS,
                (long long)NTOK*3*DIMC, HDIM,
                (long long)NTOK*3*DIMC, HDIM,
                (long long)NHEADS*NN, NN,
                0.125f, true, false);

    softmax2048<<<BATCHN*NHEADS*NTOK, 256>>>(sc);

    /* out_heads = attn @ v -> bufB[T, C] (interleaved heads) */
    launch_gemm(sc, qkv + 2*DIMC /*v*/, bufB, nullptr,
                NTOK, HDIM, NTOK, NTOK, 3*DIMC, DIMC,
                BATCHN*NHEADS, NHEADS,
                (long long)NHEADS*NN, NN,
                (long long)NTOK*3*DIMC, HDIM,
                TC, HDIM,
                1.0f, false, false);

    /* proj */
    launch_gemm(bufB, proj_w, bufA, proj_b, TTOK, DIMC, DIMC,
                DIMC, DIMC, DIMC, 1, 1, 0,0, 0,0, 0,0, 1.0f, false, false);
    add_vec<<<nElemBlks, 256>>>(out, x, bufA);        /* out = x + mha */

    /* ---- sublayer 2: kernel attention (full channel) ---- */
    float* bq = qkv;
    float* bk = qkv + (size_t)TTOK * DIMC;
    float* bv = qkv + (size_t)2 * TTOK * DIMC;
    launch_gemm(out, kq_w, bq, kq_b, TTOK, DIMC, DIMC, DIMC, DIMC, DIMC,
                1, 1, 0,0, 0,0, 0,0, 1.0f, false, false);
    launch_gemm(out, kk_w, bk, kk_b, TTOK, DIMC, DIMC, DIMC, DIMC, DIMC,
                1, 1, 0,0, 0,0, 0,0, 1.0f, false, false);
    launch_gemm(out, kv_w, bv, kv_b, TTOK, DIMC, DIMC, DIMC, DIMC, DIMC,
                1, 1, 0,0, 0,0, 0,0, 1.0f, false, false);

    /* qk = q @ k^T per batch (K = 1024) */
    launch_gemm(bq, bk, sc, nullptr, NTOK, NTOK, DIMC, DIMC, DIMC, NTOK,
                BATCHN, 1, TC, 0, TC, 0, NN, 0, 1.0f, true, false);

    theta_softmax2048<<<BATCHN*NTOK, 256>>>(sc);

    /* av = attn @ v per batch */
    launch_gemm(sc, bv, bufB, nullptr, NTOK, DIMC, NTOK, NTOK, DIMC, DIMC,
                BATCHN, 1, NN, 0, TC, 0, TC, 0, 1.0f, false, false);

    launch_gemm(bufB, ko_w, bufA, ko_b, TTOK, DIMC, DIMC, DIMC, DIMC, DIMC,
                1, 1, 0,0, 0,0, 0,0, 1.0f, false, false);
    add_vec<<<nElemBlks, 256>>>(out, out, bufA);      /* out += kernel_attn */

    /* ---- sublayer 3: FFN ---- */
    layernorm1024<<<TTOK, 256>>>(out, ln2_g, ln2_b, bufA);
    launch_gemm(bufA, fc1_w, ff, fc1_b, TTOK, DFF, DIMC, DIMC, DFF, DFF,
                1, 1, 0,0, 0,0, 0,0, 1.0f, false, true /*gelu*/);
    launch_gemm(ff, fc2_w, bufA, fc2_b, TTOK, DIMC, DFF, DFF, DIMC, DIMC,
                1, 1, 0,0, 0,0, 0,0, 1.0f, false, false);
    add_vec<<<nElemBlks, 256>>>(out, out, bufA);      /* out += ffn */
}

// round 2
// speedup vs baseline: 1.0003x; 1.0003x over previous
#include <cuda_runtime.h>
#include <math.h>

#define DIMC 1024
#define NTOK 2048
#define BATCHN 2
#define TTOK (BATCHN*NTOK)   /* 4096 tokens */
#define NHEADS 16
#define HDIM 64
#define DFF 4096

/* ---------------- scratch (no allocations allowed -> device globals) ------ */
__device__ float g_bufA[(size_t)TTOK*DIMC];          /* 16 MB */
__device__ float g_bufB[(size_t)TTOK*DIMC];          /* 16 MB */
__device__ float g_qkv [(size_t)TTOK*3*DIMC];        /* 48 MB (also q/k/v for kernel-attn) */
__device__ float g_ff  [(size_t)TTOK*DFF];           /* 64 MB */
__device__ float g_sc  [(size_t)BATCHN*NHEADS*NTOK*NTOK]; /* 512 MB scores */

/* ---------------- helpers ------------------------------------------------- */
__device__ __forceinline__ float gelu_f(float x) {
    return 0.5f * x * (1.0f + erff(x * 0.7071067811865476f));
}
__device__ __forceinline__ float theta_fn(float x) {
    float sg = 1.0f / (1.0f + __expf(-x));
    float rl = fmaxf(x, 0.0f);
    return 0.5f + 0.2f * sg + 0.15f * tanhf(x) + 0.1f * rl;
}

/* ---------------- generic tiled SGEMM ------------------------------------ */
/* C[z] = alpha * A[z] (MxK) * op(B[z]) + bias ; op = B (KxN, NN) or B^T (NxK, NT)
   batch offset: off = (z/zdiv)*s1 + (z%zdiv)*s2 for each of A,B,C.
   Requires M%64==0, N%64==0, K%16==0, all row pointers 16B aligned. */
template<bool TB, bool GELU>
__global__ void __launch_bounds__(256) gemm_kernel(
    const float* __restrict__ A, const float* __restrict__ B, float* __restrict__ C,
    const float* __restrict__ bias,
    int N, int K, int lda, int ldb, int ldc, int zdiv,
    long long sA1, long long sA2, long long sB1, long long sB2,
    long long sC1, long long sC2, float alpha)
{
    __shared__ float As[16][64];
    __shared__ float Bs[16][64];
    int z  = blockIdx.z;
    int z1 = z / zdiv, z2 = z % zdiv;
    const float* Ab = A + z1 * sA1 + z2 * sA2;
    const float* Bb = B + z1 * sB1 + z2 * sB2;
    float*       Cb = C + z1 * sC1 + z2 * sC2;

    int rowBase = blockIdx.y * 64;
    int colBase = blockIdx.x * 64;
    int tid = threadIdx.x;
    int am  = tid & 63;            /* 0..63  (m for A load / n for B^T load) */
    int ak  = (tid >> 6) << 2;     /* 0,4,8,12 */
    int bn4 = (tid & 15) << 2;     /* NN B load */
    int bk  = tid >> 4;            /* 0..15 */
    int ty4 = (tid >> 4) << 2;
    int tx4 = (tid & 15) << 2;

    float acc[4][4] = {};
    const float* aPtr = Ab + (long long)(rowBase + am) * lda + ak;

    for (int k0 = 0; k0 < K; k0 += 16) {
        float4 av = *(const float4*)(aPtr + k0);
        As[ak+0][am] = av.x; As[ak+1][am] = av.y;
        As[ak+2][am] = av.z; As[ak+3][am] = av.w;
        if (TB) {
            float4 bv = *(const float4*)(Bb + (long long)(colBase + am) * ldb + k0 + ak);
            Bs[ak+0][am] = bv.x; Bs[ak+1][am] = bv.y;
            Bs[ak+2][am] = bv.z; Bs[ak+3][am] = bv.w;
        } else {
            float4 bv = *(const float4*)(Bb + (long long)(k0 + bk) * ldb + colBase + bn4);
            *(float4*)&Bs[bk][bn4] = bv;
        }
        __syncthreads();
        #pragma unroll
        for (int kk = 0; kk < 16; kk++) {
            float4 ra = *(const float4*)&As[kk][ty4];
            float4 rb = *(const float4*)&Bs[kk][tx4];
            acc[0][0] += ra.x*rb.x; acc[0][1] += ra.x*rb.y; acc[0][2] += ra.x*rb.z; acc[0][3] += ra.x*rb.w;
            acc[1][0] += ra.y*rb.x; acc[1][1] += ra.y*rb.y; acc[1][2] += ra.y*rb.z; acc[1][3] += ra.y*rb.w;
            acc[2][0] += ra.z*rb.x; acc[2][1] += ra.z*rb.y; acc[2][2] += ra.z*rb.z; acc[2][3] += ra.z*rb.w;
            acc[3][0] += ra.w*rb.x; acc[3][1] += ra.w*rb.y; acc[3][2] += ra.w*rb.z; acc[3][3] += ra.w*rb.w;
        }
        __syncthreads();
    }

    float4 bvv = make_float4(0.f, 0.f, 0.f, 0.f);
    if (bias) bvv = *(const float4*)(bias + colBase + tx4);
    #pragma unroll
    for (int i = 0; i < 4; i++) {
        float4 o;
        o.x = acc[i][0] * alpha + bvv.x;
        o.y = acc[i][1] * alpha + bvv.y;
        o.z = acc[i][2] * alpha + bvv.z;
        o.w = acc[i][3] * alpha + bvv.w;
        if (GELU) { o.x = gelu_f(o.x); o.y = gelu_f(o.y); o.z = gelu_f(o.z); o.w = gelu_f(o.w); }
        *(float4*)(Cb + (long long)(rowBase + ty4 + i) * ldc + colBase + tx4) = o;
    }
}

/* ---------------- row softmax over 2048 (in place) ------------------------ */
__global__ void __launch_bounds__(256) softmax2048(float* __restrict__ S)
{
    __shared__ float red[8];
    float* row = S + (long long)blockIdx.x * 2048;
    int tid = threadIdx.x;
    float4 v0 = ((float4*)row)[tid];
    float4 v1 = ((float4*)row)[tid + 256];
    float m = fmaxf(fmaxf(fmaxf(v0.x, v0.y), fmaxf(v0.z, v0.w)),
                    fmaxf(fmaxf(v1.x, v1.y), fmaxf(v1.z, v1.w)));
    #pragma unroll
    for (int o = 16; o; o >>= 1) m = fmaxf(m, __shfl_xor_sync(0xffffffffu, m, o));
    if ((tid & 31) == 0) red[tid >> 5] = m;
    __syncthreads();
    m = fmaxf(fmaxf(fmaxf(red[0], red[1]), fmaxf(red[2], red[3])),
              fmaxf(fmaxf(red[4], red[5]), fmaxf(red[6], red[7])));
    v0.x = __expf(v0.x - m); v0.y = __expf(v0.y - m); v0.z = __expf(v0.z - m); v0.w = __expf(v0.w - m);
    v1.x = __expf(v1.x - m); v1.y = __expf(v1.y - m); v1.z = __expf(v1.z - m); v1.w = __expf(v1.w - m);
    float s = v0.x + v0.y + v0.z + v0.w + v1.x + v1.y + v1.z + v1.w;
    #pragma unroll
    for (int o = 16; o; o >>= 1) s += __shfl_xor_sync(0xffffffffu, s, o);
    __syncthreads();
    if ((tid & 31) == 0) red[tid >> 5] = s;
    __syncthreads();
    s = red[0] + red[1] + red[2] + red[3] + red[4] + red[5] + red[6] + red[7];
    float r = 1.0f / s;
    v0.x *= r; v0.y *= r; v0.z *= r; v0.w *= r;
    v1.x *= r; v1.y *= r; v1.z *= r; v1.w *= r;
    ((float4*)row)[tid] = v0;
    ((float4*)row)[tid + 256] = v1;
}

/* ---------------- theta transform + row softmax over 2048 ---------------- */
__global__ void __launch_bounds__(256) theta_softmax2048(float* __restrict__ S)
{
    __shared__ float red[8];
    float* row = S + (long long)blockIdx.x * 2048;
    int tid = threadIdx.x;
    float4 v0 = ((float4*)row)[tid];
    float4 v1 = ((float4*)row)[tid + 256];
    v0.x = theta_fn(v0.x); v0.y = theta_fn(v0.y); v0.z = theta_fn(v0.z); v0.w = theta_fn(v0.w);
    v1.x = theta_fn(v1.x); v1.y = theta_fn(v1.y); v1.z = theta_fn(v1.z); v1.w = theta_fn(v1.w);
    float m = fmaxf(fmaxf(fmaxf(v0.x, v0.y), fmaxf(v0.z, v0.w)),
                    fmaxf(fmaxf(v1.x, v1.y), fmaxf(v1.z, v1.w)));
    #pragma unroll
    for (int o = 16; o; o >>= 1) m = fmaxf(m, __shfl_xor_sync(0xffffffffu, m, o));
    if ((tid & 31) == 0) red[tid >> 5] = m;
    __syncthreads();
    m = fmaxf(fmaxf(fmaxf(red[0], red[1]), fmaxf(red[2], red[3])),
              fmaxf(fmaxf(red[4], red[5]), fmaxf(red[6], red[7])));
    v0.x = __expf(v0.x - m); v0.y = __expf(v0.y - m); v0.z = __expf(v0.z - m); v0.w = __expf(v0.w - m);
    v1.x = __expf(v1.x - m); v1.y = __expf(v1.y - m); v1.z = __expf(v1.z - m); v1.w = __expf(v1.w - m);
    float s = v0.x + v0.y + v0.z + v0.w + v1.x + v1.y + v1.z + v1.w;
    #pragma unroll
    for (int o = 16; o; o >>= 1) s += __shfl_xor_sync(0xffffffffu, s, o);
    __syncthreads();
    if ((tid & 31) == 0) red[tid >> 5] = s;
    __syncthreads();
    s = red[0] + red[1] + red[2] + red[3] + red[4] + red[5] + red[6] + red[7];
    float r = 1.0f / s;
    v0.x *= r; v0.y *= r; v0.z *= r; v0.w *= r;
    v1.x *= r; v1.y *= r; v1.z *= r; v1.w *= r;
    ((float4*)row)[tid] = v0;
    ((float4*)row)[tid + 256] = v1;
}

/* ---------------- LayerNorm over 1024 ------------------------------------ */
__global__ void __launch_bounds__(256) layernorm1024(
    const float* __restrict__ X, const float* __restrict__ g,
    const float* __restrict__ bta, float* __restrict__ Y)
{
    __shared__ float rs[8], rq[8];
    long long base = (long long)blockIdx.x * 1024;
    int tid = threadIdx.x;
    float4 v = *(const float4*)(X + base + tid * 4);
    float s = v.x + v.y + v.z + v.w;
    float q = v.x*v.x + v.y*v.y + v.z*v.z + v.w*v.w;
    #pragma unroll
    for (int o = 16; o; o >>= 1) {
        s += __shfl_xor_sync(0xffffffffu, s, o);
        q += __shfl_xor_sync(0xffffffffu, q, o);
    }
    if ((tid & 31) == 0) { rs[tid >> 5] = s; rq[tid >> 5] = q; }
    __syncthreads();
    s = rs[0] + rs[1] + rs[2] + rs[3] + rs[4] + rs[5] + rs[6] + rs[7];
    q = rq[0] + rq[1] + rq[2] + rq[3] + rq[4] + rq[5] + rq[6] + rq[7];
    float mu  = s * (1.0f / 1024.0f);
    float var = q * (1.0f / 1024.0f) - mu * mu;
    float inv = rsqrtf(var + 1e-5f);
    float4 gg = *(const float4*)(g + tid * 4);
    float4 bb = *(const float4*)(bta + tid * 4);
    float4 o;
    o.x = (v.x - mu) * inv * gg.x + bb.x;
    o.y = (v.y - mu) * inv * gg.y + bb.y;
    o.z = (v.z - mu) * inv * gg.z + bb.z;
    o.w = (v.w - mu) * inv * gg.w + bb.w;
    *(float4*)(Y + base + tid * 4) = o;
}

/* ---------------- residual add ------------------------------------------- */
__global__ void __launch_bounds__(256) add_vec(
    float* __restrict__ out, const float* __restrict__ a, const float* __restrict__ b)
{
    int i = blockIdx.x * 256 + threadIdx.x;
    float4 av = ((const float4*)a)[i];
    float4 bv = ((const float4*)b)[i];
    av.x += bv.x; av.y += bv.y; av.z += bv.z; av.w += bv.w;
    ((float4*)out)[i] = av;
}

/* ---------------- host-side dispatch -------------------------------------- */
static inline void launch_gemm(
    const float* A, const float* B, float* C, const float* bias,
    int M, int N, int K, int lda, int ldb, int ldc,
    int batches, int zdiv,
    long long sA1, long long sA2, long long sB1, long long sB2,
    long long sC1, long long sC2,
    float alpha, bool tb, bool gelu)
{
    dim3 grid(N / 64, M / 64, batches), block(256);
    if (tb)
        gemm_kernel<true,  false><<<grid, block>>>(A, B, C, bias, N, K, lda, ldb, ldc,
                                                   zdiv, sA1, sA2, sB1, sB2, sC1, sC2, alpha);
    else if (gelu)
        gemm_kernel<false, true ><<<grid, block>>>(A, B, C, bias, N, K, lda, ldb, ldc,
                                                   zdiv, sA1, sA2, sB1, sB2, sC1, sC2, alpha);
    else
        gemm_kernel<false, false><<<grid, block>>>(A, B, C, bias, N, K, lda, ldb, ldc,
                                                   zdiv, sA1, sA2, sB1, sB2, sC1, sC2, alpha);
}

extern "C" void kernel_launch(void* const* d_in, const int* in_sizes, int n_in,
                              void* d_out, int out_size)
{
    const float* x     = (const float*)d_in[0];
    const float* ln1_g = (const float*)d_in[1];
    const float* ln1_b = (const float*)d_in[2];
    const float* qkv_w = (const float*)d_in[3];
    const float* qkv_b = (const float*)d_in[4];
    const float* proj_w= (const float*)d_in[5];
    const float* proj_b= (const float*)d_in[6];
    const float* kq_w  = (const float*)d_in[7];
    const float* kq_b  = (const float*)d_in[8];
    const float* kk_w  = (const float*)d_in[9];
    const float* kk_b  = (const float*)d_in[10];
    const float* kv_w  = (const float*)d_in[11];
    const float* kv_b  = (const float*)d_in[12];
    const float* ko_w  = (const float*)d_in[13];
    const float* ko_b  = (const float*)d_in[14];
    const float* ln2_g = (const float*)d_in[15];
    const float* ln2_b = (const float*)d_in[16];
    const float* fc1_w = (const float*)d_in[17];
    const float* fc1_b = (const float*)d_in[18];
    const float* fc2_w = (const float*)d_in[19];
    const float* fc2_b = (const float*)d_in[20];
    float* out = (float*)d_out;

    float *bufA, *bufB, *qkv, *ff, *sc;
    cudaGetSymbolAddress((void**)&bufA, g_bufA);
    cudaGetSymbolAddress((void**)&bufB, g_bufB);
    cudaGetSymbolAddress((void**)&qkv,  g_qkv);
    cudaGetSymbolAddress((void**)&ff,   g_ff);
    cudaGetSymbolAddress((void**)&sc,   g_sc);

    const long long NN   = (long long)NTOK * NTOK;
    const long long TC   = (long long)NTOK * DIMC;   /* per-batch token*dim */
    const int nElemBlks  = (TTOK * DIMC) / (4 * 256);

    /* ---- sublayer 1: MHA ---- */
    layernorm1024<<<TTOK, 256>>>(x, ln1_g, ln1_b, bufA);

    /* qkv = ln1 @ qkv_w + b  -> [T, 3072] */
    launch_gemm(bufA, qkv_w, qkv, qkv_b, TTOK, 3*DIMC, DIMC,
                DIMC, 3*DIMC, 3*DIMC, 1, 1, 0,0, 0,0, 0,0, 1.0f, false, false);

    /* per-head scores = q @ k^T * scale ; z = b*16+h */
    launch_gemm(qkv /*q*/, qkv + DIMC /*k*/, sc, nullptr,
                NTOK, NTOK, HDIM, 3*DIMC, 3*DIMC, NTOK,
                BATCHN*NHEADS, NHEADS,
                (long long)NTOK*3*DIMC, HDIM,
                (long long)NTOK*3*DIMC, HDIM,
                (long long)NHEADS*NN, NN,
                0.125f, true, false);

    softmax2048<<<BATCHN*NHEADS*NTOK, 256>>>(sc);

    /* out_heads = attn @ v -> bufB[T, C] (interleaved heads) */
    launch_gemm(sc, qkv + 2*DIMC /*v*/, bufB, nullptr,
                NTOK, HDIM, NTOK, NTOK, 3*DIMC, DIMC,
                BATCHN*NHEADS, NHEADS,
                (long long)NHEADS*NN, NN,
                (long long)NTOK*3*DIMC, HDIM,
                TC, HDIM,
                1.0f, false, false);

    /* proj */
    launch_gemm(bufB, proj_w, bufA, proj_b, TTOK, DIMC, DIMC,
                DIMC, DIMC, DIMC, 1, 1, 0,0, 0,0, 0,0, 1.0f, false, false);
    add_vec<<<nElemBlks, 256>>>(out, x, bufA);        /* out = x + mha */

    /* ---- sublayer 2: kernel attention (full channel) ---- */
    float* bq = qkv;
    float* bk = qkv + (size_t)TTOK * DIMC;
    float* bv = qkv + (size_t)2 * TTOK * DIMC;
    launch_gemm(out, kq_w, bq, kq_b, TTOK, DIMC, DIMC, DIMC, DIMC, DIMC,
                1, 1, 0,0, 0,0, 0,0, 1.0f, false, false);
    launch_gemm(out, kk_w, bk, kk_b, TTOK, DIMC, DIMC, DIMC, DIMC, DIMC,
                1, 1, 0,0, 0,0, 0,0, 1.0f, false, false);
    launch_gemm(out, kv_w, bv, kv_b, TTOK, DIMC, DIMC, DIMC, DIMC, DIMC,
                1, 1, 0,0, 0,0, 0,0, 1.0f, false, false);

    /* qk = q @ k^T per batch (K = 1024) */
    launch_gemm(bq, bk, sc, nullptr, NTOK, NTOK, DIMC, DIMC, DIMC, NTOK,
                BATCHN, 1, TC, 0, TC, 0, NN, 0, 1.0f, true, false);

    theta_softmax2048<<<BATCHN*NTOK, 256>>>(sc);

    /* av = attn @ v per batch */
    launch_gemm(sc, bv, bufB, nullptr, NTOK, DIMC, NTOK, NTOK, DIMC, DIMC,
                BATCHN, 1, NN, 0, TC, 0, TC, 0, 1.0f, false, false);

    launch_gemm(bufB, ko_w, bufA, ko_b, TTOK, DIMC, DIMC, DIMC, DIMC, DIMC,
                1, 1, 0,0, 0,0, 0,0, 1.0f, false, false);
    add_vec<<<nElemBlks, 256>>>(out, out, bufA);      /* out += kernel_attn */

    /* ---- sublayer 3: FFN ---- */
    layernorm1024<<<TTOK, 256>>>(out, ln2_g, ln2_b, bufA);
    launch_gemm(bufA, fc1_w, ff, fc1_b, TTOK, DFF, DIMC, DIMC, DFF, DFF,
                1, 1, 0,0, 0,0, 0,0, 1.0f, false, true /*gelu*/);
    launch_gemm(ff, fc2_w, bufA, fc2_b, TTOK, DIMC, DFF, DFF, DIMC, DIMC,
                1, 1, 0,0, 0,0, 0,0, 1.0f, false, false);
    add_vec<<<nElemBlks, 256>>>(out, out, bufA);      /* out += ffn */
}

// round 3
// speedup vs baseline: 2.9723x; 2.9714x over previous
#include <cuda_runtime.h>
#include <cuda_bf16.h>
#include <math.h>

#define DIMC 1024
#define NTOK 2048
#define BATCHN 2
#define TTOK (BATCHN*NTOK)   /* 4096 tokens */
#define NHEADS 16
#define HDIM 64
#define DFF 4096

/* ---------------- scratch (no allocations allowed -> device globals) ------ */
__device__ float g_bufA[(size_t)TTOK*DIMC];          /* 16 MB */
__device__ float g_bufB[(size_t)TTOK*DIMC];          /* 16 MB */
__device__ float g_qkv [(size_t)TTOK*3*DIMC];        /* 48 MB */
__device__ float g_ff  [(size_t)TTOK*DFF];           /* 64 MB */
__device__ float g_sc  [(size_t)BATCHN*NHEADS*NTOK*NTOK]; /* 512 MB scores */

/* ---------------- helpers ------------------------------------------------- */
__device__ __forceinline__ float gelu_f(float x) {
    return 0.5f * x * (1.0f + erff(x * 0.7071067811865476f));
}
__device__ __forceinline__ float theta_fn(float x) {
    float sg = 1.0f / (1.0f + __expf(-x));
    float rl = fmaxf(x, 0.0f);
    return 0.5f + 0.2f * sg + 0.15f * tanhf(x) + 0.1f * rl;
}

/* split fp32 pair into (hi, lo) bf16x2 packed words */
__device__ __forceinline__ void split2(float x, float y, unsigned& hi, unsigned& lo) {
    __nv_bfloat16 hx = __float2bfloat16(x);
    __nv_bfloat16 hy = __float2bfloat16(y);
    __nv_bfloat16 lx = __float2bfloat16(x - __bfloat162float(hx));
    __nv_bfloat16 ly = __float2bfloat16(y - __bfloat162float(hy));
    __nv_bfloat162 h; h.x = hx; h.y = hy;
    __nv_bfloat162 l; l.x = lx; l.y = ly;
    hi = *(unsigned*)&h;
    lo = *(unsigned*)&l;
}

__device__ __forceinline__ void ldsm4(unsigned& r0, unsigned& r1, unsigned& r2, unsigned& r3, unsigned a) {
    asm volatile("ldmatrix.sync.aligned.m8n8.x4.shared.b16 {%0,%1,%2,%3}, [%4];"
                 : "=r"(r0), "=r"(r1), "=r"(r2), "=r"(r3) : "r"(a));
}
__device__ __forceinline__ void ldsm4t(unsigned& r0, unsigned& r1, unsigned& r2, unsigned& r3, unsigned a) {
    asm volatile("ldmatrix.sync.aligned.m8n8.x4.trans.shared.b16 {%0,%1,%2,%3}, [%4];"
                 : "=r"(r0), "=r"(r1), "=r"(r2), "=r"(r3) : "r"(a));
}
__device__ __forceinline__ void mma16816(float* d, const unsigned* a, const unsigned* b) {
    asm volatile(
        "mma.sync.aligned.m16n8k16.row.col.f32.bf16.bf16.f32 "
        "{%0,%1,%2,%3}, {%4,%5,%6,%7}, {%8,%9}, {%0,%1,%2,%3};"
        : "+f"(d[0]), "+f"(d[1]), "+f"(d[2]), "+f"(d[3])
        : "r"(a[0]), "r"(a[1]), "r"(a[2]), "r"(a[3]), "r"(b[0]), "r"(b[1]));
}

/* ---------------- bf16x3 tensor-core GEMM ---------------------------------
   C[z] = alpha * A[z] (MxK) * op(B[z]) + bias ; op = B (KxN) or B^T (NxK).
   CTA tile: 128 x NTILE, K-tile 32. fp32 inputs split to bf16 hi/lo in smem;
   3 MMAs per frag pair (hh + hl + lh) -> ~1e-5 relative accuracy.
   Batch: off = (z/zdiv)*s1 + (z%zdiv)*s2. M%128==0, N%NTILE==0, K%32==0.   */
template<int NTILE, bool TB, bool GELU>
__global__ void __launch_bounds__(256) mma_gemm(
    const float* __restrict__ A, const float* __restrict__ B, float* __restrict__ C,
    const float* __restrict__ bias,
    int K, int lda, int ldb, int ldc, int zdiv,
    long long sA1, long long sA2, long long sB1, long long sB2,
    long long sC1, long long sC2, float alpha)
{
    /* As: 128 rows x 128B  (hi chunks 0-3, lo chunks 4-7, 16B chunks, XOR swizzle)
       Bs NN: hi tile [32 rows x 256B] at 0, lo tile at +8192 (chunk idx n/8 ^ (k&7))
       Bs TB: A-style [NTILE rows x 128B hi|lo]                                    */
    __shared__ __align__(16) char As[16384];
    __shared__ __align__(16) char Bs[16384];

    constexpr int WROWS = (NTILE == 128) ? 2 : 4;
    constexpr int WCOLS = 8 / WROWS;
    constexpr int WTM = 128 / WROWS;       /* 64 or 32 */
    constexpr int WTN = NTILE / WCOLS;     /* 32 */
    constexpr int MF = WTM / 16;           /* 4 or 2 */
    constexpr int NF = WTN / 8;            /* 4 */
    constexpr int NB = NTILE / 32;         /* B float4 loads per thread: 4 or 2 */

    int z  = blockIdx.z;
    int z1 = z / zdiv, z2 = z % zdiv;
    const float* Ab = A + z1 * sA1 + z2 * sA2;
    const float* Bb = B + z1 * sB1 + z2 * sB2;
    float*       Cb = C + z1 * sC1 + z2 * sC2;

    int rowBase = blockIdx.y * 128;
    int colBase = blockIdx.x * NTILE;
    int tid  = threadIdx.x;
    int lane = tid & 31;
    int w    = tid >> 5;
    int warpRow = (w % WROWS) * WTM;
    int warpCol = (w / WROWS) * WTN;

    float acc[MF][NF][4];
    #pragma unroll
    for (int i = 0; i < MF; i++)
        #pragma unroll
        for (int j = 0; j < NF; j++)
            #pragma unroll
            for (int r = 0; r < 4; r++) acc[i][j][r] = 0.0f;

    unsigned AsB = (unsigned)__cvta_generic_to_shared(As);
    unsigned BsB = (unsigned)__cvta_generic_to_shared(Bs);

    float4 pa[4], pb[NB];

    /* prefetch first tiles into registers */
    #pragma unroll
    for (int i = 0; i < 4; i++) {
        int lin = tid + i * 256, r = lin >> 3, c4 = lin & 7;
        pa[i] = *(const float4*)(Ab + (long long)(rowBase + r) * lda + c4 * 4);
    }
    #pragma unroll
    for (int i = 0; i < NB; i++) {
        int lin = tid + i * 256;
        if (TB) {
            int r = lin >> 3, c4 = lin & 7;
            pb[i] = *(const float4*)(Bb + (long long)(colBase + r) * ldb + c4 * 4);
        } else {
            int r = lin / (NTILE / 4), c4 = lin % (NTILE / 4);
            pb[i] = *(const float4*)(Bb + (long long)r * ldb + colBase + c4 * 4);
        }
    }

    for (int k0 = 0; k0 < K; k0 += 32) {
        /* ---- store prefetched regs -> smem (split hi/lo) ---- */
        #pragma unroll
        for (int i = 0; i < 4; i++) {
            int lin = tid + i * 256, r = lin >> 3, c4 = lin & 7;
            unsigned h01, l01, h23, l23;
            split2(pa[i].x, pa[i].y, h01, l01);
            split2(pa[i].z, pa[i].w, h23, l23);
            int ch = c4 >> 1, boff = (c4 & 1) * 8;
            *(uint2*)(As + r * 128 + (((ch    ) ^ (r & 7)) << 4) + boff) = make_uint2(h01, h23);
            *(uint2*)(As + r * 128 + (((ch + 4) ^ (r & 7)) << 4) + boff) = make_uint2(l01, l23);
        }
        #pragma unroll
        for (int i = 0; i < NB; i++) {
            int lin = tid + i * 256;
            unsigned h01, l01, h23, l23;
            split2(pb[i].x, pb[i].y, h01, l01);
            split2(pb[i].z, pb[i].w, h23, l23);
            if (TB) {
                int r = lin >> 3, c4 = lin & 7, ch = c4 >> 1, boff = (c4 & 1) * 8;
                *(uint2*)(Bs + r * 128 + (((ch    ) ^ (r & 7)) << 4) + boff) = make_uint2(h01, h23);
                *(uint2*)(Bs + r * 128 + (((ch + 4) ^ (r & 7)) << 4) + boff) = make_uint2(l01, l23);
            } else {
                int r = lin / (NTILE / 4), c4 = lin % (NTILE / 4), ch = c4 >> 1, boff = (c4 & 1) * 8;
                *(uint2*)(Bs +        r * 256 + ((ch ^ (r & 7)) << 4) + boff) = make_uint2(h01, h23);
                *(uint2*)(Bs + 8192 + r * 256 + ((ch ^ (r & 7)) << 4) + boff) = make_uint2(l01, l23);
            }
        }
        __syncthreads();

        /* ---- prefetch next K-tile ---- */
        if (k0 + 32 < K) {
            int kn = k0 + 32;
            #pragma unroll
            for (int i = 0; i < 4; i++) {
                int lin = tid + i * 256, r = lin >> 3, c4 = lin & 7;
                pa[i] = *(const float4*)(Ab + (long long)(rowBase + r) * lda + kn + c4 * 4);
            }
            #pragma unroll
            for (int i = 0; i < NB; i++) {
                int lin = tid + i * 256;
                if (TB) {
                    int r = lin >> 3, c4 = lin & 7;
                    pb[i] = *(const float4*)(Bb + (long long)(colBase + r) * ldb + kn + c4 * 4);
                } else {
                    int r = lin / (NTILE / 4), c4 = lin % (NTILE / 4);
                    pb[i] = *(const float4*)(Bb + (long long)(kn + r) * ldb + colBase + c4 * 4);
                }
            }
        }

        /* ---- compute: 2 k-steps of 16, 3 MMAs per frag pair ---- */
        #pragma unroll
        for (int ks = 0; ks < 2; ks++) {
            unsigned ah[MF][4], al[MF][4];
            #pragma unroll
            for (int mf = 0; mf < MF; mf++) {
                int ar = warpRow + mf * 16 + (lane & 15);
                int ac = ks * 2 + (lane >> 4);
                ldsm4(ah[mf][0], ah[mf][1], ah[mf][2], ah[mf][3],
                      AsB + ar * 128 + (((ac    ) ^ (ar & 7)) << 4));
                ldsm4(al[mf][0], al[mf][1], al[mf][2], al[mf][3],
                      AsB + ar * 128 + (((ac + 4) ^ (ar & 7)) << 4));
            }
            unsigned bh[NF][2], bl[NF][2];
            #pragma unroll
            for (int np = 0; np < NF / 2; np++) {
                if (!TB) {
                    int bk = ks * 16 + (lane & 15);
                    int nc = (warpCol + np * 16 + ((lane >> 4) << 3)) >> 3;
                    unsigned ad = BsB + bk * 256 + ((nc ^ (bk & 7)) << 4);
                    ldsm4t(bh[2*np][0], bh[2*np][1], bh[2*np+1][0], bh[2*np+1][1], ad);
                    ldsm4t(bl[2*np][0], bl[2*np][1], bl[2*np+1][0], bl[2*np+1][1], ad + 8192);
                } else {
                    int br = warpCol + np * 16 + ((lane >> 4) << 3) + (lane & 7);
                    int kc = ks * 2 + ((lane >> 3) & 1);
                    ldsm4(bh[2*np][0], bh[2*np][1], bh[2*np+1][0], bh[2*np+1][1],
                          BsB + br * 128 + (((kc    ) ^ (br & 7)) << 4));
                    ldsm4(bl[2*np][0], bl[2*np][1], bl[2*np+1][0], bl[2*np+1][1],
                          BsB + br * 128 + (((kc + 4) ^ (br & 7)) << 4));
                }
            }
            #pragma unroll
            for (int mf = 0; mf < MF; mf++)
                #pragma unroll
                for (int nf = 0; nf < NF; nf++) {
                    mma16816(acc[mf][nf], ah[mf], bh[nf]);
                    mma16816(acc[mf][nf], ah[mf], bl[nf]);
                    mma16816(acc[mf][nf], al[mf], bh[nf]);
                }
        }
        __syncthreads();
    }

    /* ---- epilogue: alpha, bias, gelu, store float2 ---- */
    #pragma unroll
    for (int mf = 0; mf < MF; mf++) {
        #pragma unroll
        for (int nf = 0; nf < NF; nf++) {
            int row = rowBase + warpRow + mf * 16 + (lane >> 2);
            int col = colBase + warpCol + nf * 8 + (lane & 3) * 2;
            float bx = 0.f, by = 0.f;
            if (bias) { float2 bb = *(const float2*)(bias + col); bx = bb.x; by = bb.y; }
            float v0 = acc[mf][nf][0] * alpha + bx;
            float v1 = acc[mf][nf][1] * alpha + by;
            float v2 = acc[mf][nf][2] * alpha + bx;
            float v3 = acc[mf][nf][3] * alpha + by;
            if (GELU) { v0 = gelu_f(v0); v1 = gelu_f(v1); v2 = gelu_f(v2); v3 = gelu_f(v3); }
            *(float2*)(Cb + (long long)row * ldc + col)       = make_float2(v0, v1);
            *(float2*)(Cb + (long long)(row + 8) * ldc + col) = make_float2(v2, v3);
        }
    }
}

/* ---------------- row softmax over 2048 (in place) ------------------------ */
__global__ void __launch_bounds__(256) softmax2048(float* __restrict__ S)
{
    __shared__ float red[8];
    float* row = S + (long long)blockIdx.x * 2048;
    int tid = threadIdx.x;
    float4 v0 = ((float4*)row)[tid];
    float4 v1 = ((float4*)row)[tid + 256];
    float m = fmaxf(fmaxf(fmaxf(v0.x, v0.y), fmaxf(v0.z, v0.w)),
                    fmaxf(fmaxf(v1.x, v1.y), fmaxf(v1.z, v1.w)));
    #pragma unroll
    for (int o = 16; o; o >>= 1) m = fmaxf(m, __shfl_xor_sync(0xffffffffu, m, o));
    if ((tid & 31) == 0) red[tid >> 5] = m;
    __syncthreads();
    m = fmaxf(fmaxf(fmaxf(red[0], red[1]), fmaxf(red[2], red[3])),
              fmaxf(fmaxf(red[4], red[5]), fmaxf(red[6], red[7])));
    v0.x = __expf(v0.x - m); v0.y = __expf(v0.y - m); v0.z = __expf(v0.z - m); v0.w = __expf(v0.w - m);
    v1.x = __expf(v1.x - m); v1.y = __expf(v1.y - m); v1.z = __expf(v1.z - m); v1.w = __expf(v1.w - m);
    float s = v0.x + v0.y + v0.z + v0.w + v1.x + v1.y + v1.z + v1.w;
    #pragma unroll
    for (int o = 16; o; o >>= 1) s += __shfl_xor_sync(0xffffffffu, s, o);
    __syncthreads();
    if ((tid & 31) == 0) red[tid >> 5] = s;
    __syncthreads();
    s = red[0] + red[1] + red[2] + red[3] + red[4] + red[5] + red[6] + red[7];
    float r = 1.0f / s;
    v0.x *= r; v0.y *= r; v0.z *= r; v0.w *= r;
    v1.x *= r; v1.y *= r; v1.z *= r; v1.w *= r;
    ((float4*)row)[tid] = v0;
    ((float4*)row)[tid + 256] = v1;
}

/* ---------------- theta transform + row softmax over 2048 ---------------- */
__global__ void __launch_bounds__(256) theta_softmax2048(float* __restrict__ S)
{
    __shared__ float red[8];
    float* row = S + (long long)blockIdx.x * 2048;
    int tid = threadIdx.x;
    float4 v0 = ((float4*)row)[tid];
    float4 v1 = ((float4*)row)[tid + 256];
    v0.x = theta_fn(v0.x); v0.y = theta_fn(v0.y); v0.z = theta_fn(v0.z); v0.w = theta_fn(v0.w);
    v1.x = theta_fn(v1.x); v1.y = theta_fn(v1.y); v1.z = theta_fn(v1.z); v1.w = theta_fn(v1.w);
    float m = fmaxf(fmaxf(fmaxf(v0.x, v0.y), fmaxf(v0.z, v0.w)),
                    fmaxf(fmaxf(v1.x, v1.y), fmaxf(v1.z, v1.w)));
    #pragma unroll
    for (int o = 16; o; o >>= 1) m = fmaxf(m, __shfl_xor_sync(0xffffffffu, m, o));
    if ((tid & 31) == 0) red[tid >> 5] = m;
    __syncthreads();
    m = fmaxf(fmaxf(fmaxf(red[0], red[1]), fmaxf(red[2], red[3])),
              fmaxf(fmaxf(red[4], red[5]), fmaxf(red[6], red[7])));
    v0.x = __expf(v0.x - m); v0.y = __expf(v0.y - m); v0.z = __expf(v0.z - m); v0.w = __expf(v0.w - m);
    v1.x = __expf(v1.x - m); v1.y = __expf(v1.y - m); v1.z = __expf(v1.z - m); v1.w = __expf(v1.w - m);
    float s = v0.x + v0.y + v0.z + v0.w + v1.x + v1.y + v1.z + v1.w;
    #pragma unroll
    for (int o = 16; o; o >>= 1) s += __shfl_xor_sync(0xffffffffu, s, o);
    __syncthreads();
    if ((tid & 31) == 0) red[tid >> 5] = s;
    __syncthreads();
    s = red[0] + red[1] + red[2] + red[3] + red[4] + red[5] + red[6] + red[7];
    float r = 1.0f / s;
    v0.x *= r; v0.y *= r; v0.z *= r; v0.w *= r;
    v1.x *= r; v1.y *= r; v1.z *= r; v1.w *= r;
    ((float4*)row)[tid] = v0;
    ((float4*)row)[tid + 256] = v1;
}

/* ---------------- LayerNorm over 1024 ------------------------------------ */
__global__ void __launch_bounds__(256) layernorm1024(
    const float* __restrict__ X, const float* __restrict__ g,
    const float* __restrict__ bta, float* __restrict__ Y)
{
    __shared__ float rs[8], rq[8];
    long long base = (long long)blockIdx.x * 1024;
    int tid = threadIdx.x;
    float4 v = *(const float4*)(X + base + tid * 4);
    float s = v.x + v.y + v.z + v.w;
    float q = v.x*v.x + v.y*v.y + v.z*v.z + v.w*v.w;
    #pragma unroll
    for (int o = 16; o; o >>= 1) {
        s += __shfl_xor_sync(0xffffffffu, s, o);
        q += __shfl_xor_sync(0xffffffffu, q, o);
    }
    if ((tid & 31) == 0) { rs[tid >> 5] = s; rq[tid >> 5] = q; }
    __syncthreads();
    s = rs[0] + rs[1] + rs[2] + rs[3] + rs[4] + rs[5] + rs[6] + rs[7];
    q = rq[0] + rq[1] + rq[2] + rq[3] + rq[4] + rq[5] + rq[6] + rq[7];
    float mu  = s * (1.0f / 1024.0f);
    float var = q * (1.0f / 1024.0f) - mu * mu;
    float inv = rsqrtf(var + 1e-5f);
    float4 gg = *(const float4*)(g + tid * 4);
    float4 bb = *(const float4*)(bta + tid * 4);
    float4 o;
    o.x = (v.x - mu) * inv * gg.x + bb.x;
    o.y = (v.y - mu) * inv * gg.y + bb.y;
    o.z = (v.z - mu) * inv * gg.z + bb.z;
    o.w = (v.w - mu) * inv * gg.w + bb.w;
    *(float4*)(Y + base + tid * 4) = o;
}

/* ---------------- residual add ------------------------------------------- */
__global__ void __launch_bounds__(256) add_vec(
    float* __restrict__ out, const float* __restrict__ a, const float* __restrict__ b)
{
    int i = blockIdx.x * 256 + threadIdx.x;
    float4 av = ((const float4*)a)[i];
    float4 bv = ((const float4*)b)[i];
    av.x += bv.x; av.y += bv.y; av.z += bv.z; av.w += bv.w;
    ((float4*)out)[i] = av;
}

/* ---------------- host-side dispatch -------------------------------------- */
static inline void launch_gemm(
    const float* A, const float* B, float* C, const float* bias,
    int M, int N, int K, int lda, int ldb, int ldc,
    int batches, int zdiv,
    long long sA1, long long sA2, long long sB1, long long sB2,
    long long sC1, long long sC2,
    float alpha, bool tb, bool gelu)
{
    dim3 block(256);
    if (N % 128 == 0) {
        dim3 grid(N / 128, M / 128, batches);
        if (tb)
            mma_gemm<128, true,  false><<<grid, block>>>(A, B, C, bias, K, lda, ldb, ldc,
                zdiv, sA1, sA2, sB1, sB2, sC1, sC2, alpha);
        else if (gelu)
            mma_gemm<128, false, true ><<<grid, block>>>(A, B, C, bias, K, lda, ldb, ldc,
                zdiv, sA1, sA2, sB1, sB2, sC1, sC2, alpha);
        else
            mma_gemm<128, false, false><<<grid, block>>>(A, B, C, bias, K, lda, ldb, ldc,
                zdiv, sA1, sA2, sB1, sB2, sC1, sC2, alpha);
    } else {
        dim3 grid(N / 64, M / 128, batches);
        mma_gemm<64, false, false><<<grid, block>>>(A, B, C, bias, K, lda, ldb, ldc,
            zdiv, sA1, sA2, sB1, sB2, sC1, sC2, alpha);
    }
}

extern "C" void kernel_launch(void* const* d_in, const int* in_sizes, int n_in,
                              void* d_out, int out_size)
{
    const float* x     = (const float*)d_in[0];
    const float* ln1_g = (const float*)d_in[1];
    const float* ln1_b = (const float*)d_in[2];
    const float* qkv_w = (const float*)d_in[3];
    const float* qkv_b = (const float*)d_in[4];
    const float* proj_w= (const float*)d_in[5];
    const float* proj_b= (const float*)d_in[6];
    const float* kq_w  = (const float*)d_in[7];
    const float* kq_b  = (const float*)d_in[8];
    const float* kk_w  = (const float*)d_in[9];
    const float* kk_b  = (const float*)d_in[10];
    const float* kv_w  = (const float*)d_in[11];
    const float* kv_b  = (const float*)d_in[12];
    const float* ko_w  = (const float*)d_in[13];
    const float* ko_b  = (const float*)d_in[14];
    const float* ln2_g = (const float*)d_in[15];
    const float* ln2_b = (const float*)d_in[16];
    const float* fc1_w = (const float*)d_in[17];
    const float* fc1_b = (const float*)d_in[18];
    const float* fc2_w = (const float*)d_in[19];
    const float* fc2_b = (const float*)d_in[20];
    float* out = (float*)d_out;

    float *bufA, *bufB, *qkv, *ff, *sc;
    cudaGetSymbolAddress((void**)&bufA, g_bufA);
    cudaGetSymbolAddress((void**)&bufB, g_bufB);
    cudaGetSymbolAddress((void**)&qkv,  g_qkv);
    cudaGetSymbolAddress((void**)&ff,   g_ff);
    cudaGetSymbolAddress((void**)&sc,   g_sc);

    const long long NN   = (long long)NTOK * NTOK;
    const long long TC   = (long long)NTOK * DIMC;   /* per-batch token*dim */
    const int nElemBlks  = (TTOK * DIMC) / (4 * 256);

    /* ---- sublayer 1: MHA ---- */
    layernorm1024<<<TTOK, 256>>>(x, ln1_g, ln1_b, bufA);

    /* qkv = ln1 @ qkv_w + b  -> [T, 3072] */
    launch_gemm(bufA, qkv_w, qkv, qkv_b, TTOK, 3*DIMC, DIMC,
                DIMC, 3*DIMC, 3*DIMC, 1, 1, 0,0, 0,0, 0,0, 1.0f, false, false);

    /* per-head scores = q @ k^T * scale ; z = b*16+h */
    launch_gemm(qkv /*q*/, qkv + DIMC /*k*/, sc, nullptr,
                NTOK, NTOK, HDIM, 3*DIMC, 3*DIMC, NTOK,
                BATCHN*NHEADS, NHEADS,
                (long long)NTOK*3*DIMC, HDIM,
                (long long)NTOK*3*DIMC, HDIM,
                (long long)NHEADS*NN, NN,
                0.125f, true, false);

    softmax2048<<<BATCHN*NHEADS*NTOK, 256>>>(sc);

    /* out_heads = attn @ v -> bufB[T, C] (interleaved heads) */
    launch_gemm(sc, qkv + 2*DIMC /*v*/, bufB, nullptr,
                NTOK, HDIM, NTOK, NTOK, 3*DIMC, DIMC,
                BATCHN*NHEADS, NHEADS,
                (long long)NHEADS*NN, NN,
                (long long)NTOK*3*DIMC, HDIM,
                TC, HDIM,
                1.0f, false, false);

    /* proj */
    launch_gemm(bufB, proj_w, bufA, proj_b, TTOK, DIMC, DIMC,
                DIMC, DIMC, DIMC, 1, 1, 0,0, 0,0, 0,0, 1.0f, false, false);
    add_vec<<<nElemBlks, 256>>>(out, x, bufA);        /* out = x + mha */

    /* ---- sublayer 2: kernel attention (full channel) ---- */
    float* bq = qkv;
    float* bk = qkv + (size_t)TTOK * DIMC;
    float* bv = qkv + (size_t)2 * TTOK * DIMC;
    launch_gemm(out, kq_w, bq, kq_b, TTOK, DIMC, DIMC, DIMC, DIMC, DIMC,
                1, 1, 0,0, 0,0, 0,0, 1.0f, false, false);
    launch_gemm(out, kk_w, bk, kk_b, TTOK, DIMC, DIMC, DIMC, DIMC, DIMC,
                1, 1, 0,0, 0,0, 0,0, 1.0f, false, false);
    launch_gemm(out, kv_w, bv, kv_b, TTOK, DIMC, DIMC, DIMC, DIMC, DIMC,
                1, 1, 0,0, 0,0, 0,0, 1.0f, false, false);

    /* qk = q @ k^T per batch (K = 1024) */
    launch_gemm(bq, bk, sc, nullptr, NTOK, NTOK, DIMC, DIMC, DIMC, NTOK,
                BATCHN, 1, TC, 0, TC, 0, NN, 0, 1.0f, true, false);

    theta_softmax2048<<<BATCHN*NTOK, 256>>>(sc);

    /* av = attn @ v per batch */
    launch_gemm(sc, bv, bufB, nullptr, NTOK, DIMC, NTOK, NTOK, DIMC, DIMC,
                BATCHN, 1, NN, 0, TC, 0, TC, 0, 1.0f, false, false);

    launch_gemm(bufB, ko_w, bufA, ko_b, TTOK, DIMC, DIMC, DIMC, DIMC, DIMC,
                1, 1, 0,0, 0,0, 0,0, 1.0f, false, false);
    add_vec<<<nElemBlks, 256>>>(out, out, bufA);      /* out += kernel_attn */

    /* ---- sublayer 3: FFN ---- */
    layernorm1024<<<TTOK, 256>>>(out, ln2_g, ln2_b, bufA);
    launch_gemm(bufA, fc1_w, ff, fc1_b, TTOK, DFF, DIMC, DIMC, DFF, DFF,
                1, 1, 0,0, 0,0, 0,0, 1.0f, false, true /*gelu*/);
    launch_gemm(ff, fc2_w, bufA, fc2_b, TTOK, DIMC, DFF, DFF, DIMC, DIMC,
                1, 1, 0,0, 0,0, 0,0, 1.0f, false, false);
    add_vec<<<nElemBlks, 256>>>(out, out, bufA);      /* out += ffn */
}

// round 5
// speedup vs baseline: 3.1707x; 1.0668x over previous
#include <cuda_runtime.h>
#include <cuda_bf16.h>
#include <math.h>

#define DIMC 1024
#define NTOK 2048
#define BATCHN 2
#define TTOK (BATCHN*NTOK)
#define NHEADS 16
#define HDIM 64
#define DFF 4096

typedef __nv_bfloat16 bf16;
typedef __nv_bfloat162 bf162;

/* ---------------- scratch (device globals; no allocations allowed) -------- */
__device__ float g_sc  [(size_t)BATCHN*NHEADS*NTOK*NTOK];   /* 512 MB fp32 scores */
__device__ float g_bufA[(size_t)TTOK*DIMC];                 /* 16 MB fp32 */
__device__ bf16 g_whi[16777216],                 g_wlo[16777216];
__device__ bf16 g_lnhi [(size_t)TTOK*DIMC],      g_lnlo [(size_t)TTOK*DIMC];
__device__ bf16 g_qkvhi[(size_t)TTOK*3*DIMC],    g_qkvlo[(size_t)TTOK*3*DIMC];
__device__ bf16 g_schi [(size_t)BATCHN*NHEADS*NTOK*NTOK];
__device__ bf16 g_sclo [(size_t)BATCHN*NHEADS*NTOK*NTOK];
__device__ bf16 g_aohi [(size_t)TTOK*DIMC],      g_aolo [(size_t)TTOK*DIMC];
__device__ bf16 g_reshi[(size_t)TTOK*DIMC],      g_reslo[(size_t)TTOK*DIMC];
__device__ bf16 g_ffhi [(size_t)TTOK*DFF],       g_fflo [(size_t)TTOK*DFF];

/* weight element offsets inside g_whi/g_wlo (NN layout, [K,N] as given) */
#define W_QKV  0LL
#define W_PROJ 3145728LL
#define W_KQ   4194304LL
#define W_KK   5242880LL
#define W_KV   6291456LL
#define W_KO   7340032LL
#define W_FC1  8388608LL
#define W_FC2  12582912LL

/* ---------------- helpers ------------------------------------------------- */
__device__ __forceinline__ float gelu_f(float x) {
    return 0.5f * x * (1.0f + erff(x * 0.7071067811865476f));
}
__device__ __forceinline__ float theta_fn(float x) {
    float sg = 1.0f / (1.0f + __expf(-x));
    float rl = fmaxf(x, 0.0f);
    return 0.5f + 0.2f * sg + 0.15f * tanhf(x) + 0.1f * rl;
}
/* split fp32 pair -> hi/lo bf162 */
__device__ __forceinline__ void split_pair(float x, float y, bf162& h, bf162& l) {
    h.x = __float2bfloat16(x);
    h.y = __float2bfloat16(y);
    l.x = __float2bfloat16(x - __bfloat162float(h.x));
    l.y = __float2bfloat16(y - __bfloat162float(h.y));
}

__device__ __forceinline__ void ldsm4(unsigned& r0, unsigned& r1, unsigned& r2, unsigned& r3, unsigned a) {
    asm volatile("ldmatrix.sync.aligned.m8n8.x4.shared.b16 {%0,%1,%2,%3}, [%4];"
                 : "=r"(r0), "=r"(r1), "=r"(r2), "=r"(r3) : "r"(a));
}
__device__ __forceinline__ void ldsm4t(unsigned& r0, unsigned& r1, unsigned& r2, unsigned& r3, unsigned a) {
    asm volatile("ldmatrix.sync.aligned.m8n8.x4.trans.shared.b16 {%0,%1,%2,%3}, [%4];"
                 : "=r"(r0), "=r"(r1), "=r"(r2), "=r"(r3) : "r"(a));
}
__device__ __forceinline__ void mma16816(float* d, const unsigned* a, const unsigned* b) {
    asm volatile(
        "mma.sync.aligned.m16n8k16.row.col.f32.bf16.bf16.f32 "
        "{%0,%1,%2,%3}, {%4,%5,%6,%7}, {%8,%9}, {%0,%1,%2,%3};"
        : "+f"(d[0]), "+f"(d[1]), "+f"(d[2]), "+f"(d[3])
        : "r"(a[0]), "r"(a[1]), "r"(a[2]), "r"(a[3]), "r"(b[0]), "r"(b[1]));
}
__device__ __forceinline__ void cpa16(unsigned dst, const void* src) {
    asm volatile("cp.async.cg.shared.global [%0], [%1], 16;" :: "r"(dst), "l"(src));
}
#define CP_COMMIT() asm volatile("cp.async.commit_group;")
#define CP_WAIT1()  asm volatile("cp.async.wait_group 1;")

/* ---------------- bf16x3 tensor-core GEMM (cp.async 3-stage) --------------
   C[z] = alpha * A[z](M x K) * op(B[z]) + bias ; op = B [K,N] (NN) or B^T [N,K] (TB)
   All operands pre-split bf16 hi/lo. M%128==0, N%NTILE==0, K%32==0.
   smem tile layouts identical to validated R2 kernel.                       */
template<int NTILE, bool TB, bool GELU, bool OUTBF>
__global__ void __launch_bounds__(256) bgemm(
    const bf16* __restrict__ Ahi, const bf16* __restrict__ Alo,
    const bf16* __restrict__ Bhi, const bf16* __restrict__ Blo,
    float* __restrict__ C, bf16* __restrict__ Chi, bf16* __restrict__ Clo,
    const float* __restrict__ bias,
    int K, int lda, int ldb, int ldc, int zdiv,
    long long sA1, long long sA2, long long sB1, long long sB2,
    long long sC1, long long sC2, float alpha)
{
    extern __shared__ char dsm[];
    constexpr int ABYTES = 16384;            /* 128 rows x 128B (hi ch0-3 | lo ch4-7) */
    constexpr int BBYTES = NTILE * 128;
    constexpr int STAGE  = ABYTES + BBYTES;

    unsigned smRaw  = (unsigned)__cvta_generic_to_shared(dsm);
    unsigned smBase = (smRaw + 1023u) & ~1023u;

    int z = blockIdx.z, z1 = z / zdiv, z2 = z % zdiv;
    const bf16* Ah = Ahi + z1 * sA1 + z2 * sA2;
    const bf16* Al = Alo + z1 * sA1 + z2 * sA2;
    const bf16* Bh = Bhi + z1 * sB1 + z2 * sB2;
    const bf16* Bl = Blo + z1 * sB1 + z2 * sB2;
    long long coff = z1 * sC1 + z2 * sC2;

    int rowBase = blockIdx.y * 128;
    int colBase = blockIdx.x * NTILE;
    int tid = threadIdx.x, lane = tid & 31, w = tid >> 5;

    constexpr int WROWS = (NTILE == 128) ? 2 : 4;
    constexpr int WTM = 128 / WROWS;
    constexpr int MF = WTM / 16;
    constexpr int NF = 4;
    int warpRow = (w % WROWS) * WTM;
    int warpCol = (w / WROWS) * 32;

    float acc[MF][NF][4] = {};

    auto issue = [&](int s, int k0) {
        unsigned sA = smBase + s * STAGE;
        unsigned sB = sA + ABYTES;
        #pragma unroll
        for (int i = 0; i < 4; i++) {
            int li = tid + i * 256, r = li >> 3, ch = li & 7;
            const bf16* src = (ch < 4 ? Ah : Al) + (long long)(rowBase + r) * lda + k0 + (ch & 3) * 8;
            cpa16(sA + r * 128 + ((ch ^ (r & 7)) << 4), src);
        }
        if (TB) {
            #pragma unroll
            for (int i = 0; i < NTILE / 32; i++) {
                int li = tid + i * 256, r = li >> 3, ch = li & 7;
                const bf16* src = (ch < 4 ? Bh : Bl) + (long long)(colBase + r) * ldb + k0 + (ch & 3) * 8;
                cpa16(sB + r * 128 + ((ch ^ (r & 7)) << 4), src);
            }
        } else {
            #pragma unroll
            for (int i = 0; i < NTILE / 32; i++) {
                int li = tid + i * 256;
                int blk = li / (NTILE * 4);
                int idx = li % (NTILE * 4);
                int r = idx / (NTILE / 8), ch = idx % (NTILE / 8);
                const bf16* src = (blk ? Bl : Bh) + (long long)(k0 + r) * ldb + colBase + ch * 8;
                cpa16(sB + blk * (NTILE * 64) + r * (NTILE * 2) + ((ch ^ (r & 7)) << 4), src);
            }
        }
    };

    auto compute = [&](int s) {
        unsigned sA = smBase + s * STAGE;
        unsigned sB = sA + ABYTES;
        #pragma unroll
        for (int ks = 0; ks < 2; ks++) {
            unsigned ah[MF][4], al[MF][4];
            #pragma unroll
            for (int mf = 0; mf < MF; mf++) {
                int ar = warpRow + mf * 16 + (lane & 15);
                int ac = ks * 2 + (lane >> 4);
                ldsm4(ah[mf][0], ah[mf][1], ah[mf][2], ah[mf][3],
                      sA + ar * 128 + ((ac ^ (ar & 7)) << 4));
                ldsm4(al[mf][0], al[mf][1], al[mf][2], al[mf][3],
                      sA + ar * 128 + (((ac + 4) ^ (ar & 7)) << 4));
            }
            unsigned bh[NF][2], bl[NF][2];
            #pragma unroll
            for (int np = 0; np < NF / 2; np++) {
                if (!TB) {
                    int bk = ks * 16 + (lane & 15);
                    int nc = (warpCol + np * 16 + ((lane >> 4) << 3)) >> 3;
                    unsigned ad = sB + bk * (NTILE * 2) + ((nc ^ (bk & 7)) << 4);
                    ldsm4t(bh[2*np][0], bh[2*np][1], bh[2*np+1][0], bh[2*np+1][1], ad);
                    ldsm4t(bl[2*np][0], bl[2*np][1], bl[2*np+1][0], bl[2*np+1][1], ad + NTILE * 64);
                } else {
                    int br = warpCol + np * 16 + ((lane >> 4) << 3) + (lane & 7);
                    int kc = ks * 2 + ((lane >> 3) & 1);
                    ldsm4(bh[2*np][0], bh[2*np][1], bh[2*np+1][0], bh[2*np+1][1],
                          sB + br * 128 + ((kc ^ (br & 7)) << 4));
                    ldsm4(bl[2*np][0], bl[2*np][1], bl[2*np+1][0], bl[2*np+1][1],
                          sB + br * 128 + (((kc + 4) ^ (br & 7)) << 4));
                }
            }
            /* three passes -> 16 independent MMAs between same-acc reuse */
            #pragma unroll
            for (int mf = 0; mf < MF; mf++)
                #pragma unroll
                for (int nf = 0; nf < NF; nf++) mma16816(acc[mf][nf], ah[mf], bh[nf]);
            #pragma unroll
            for (int mf = 0; mf < MF; mf++)
                #pragma unroll
                for (int nf = 0; nf < NF; nf++) mma16816(acc[mf][nf], ah[mf], bl[nf]);
            #pragma unroll
            for (int mf = 0; mf < MF; mf++)
                #pragma unroll
                for (int nf = 0; nf < NF; nf++) mma16816(acc[mf][nf], al[mf], bh[nf]);
        }
    };

    int nk = K >> 5;
    issue(0, 0); CP_COMMIT();
    if (nk > 1) issue(1, 32);
    CP_COMMIT();
    for (int i = 0; i < nk; i++) {
        CP_WAIT1();
        __syncthreads();
        if (i + 2 < nk) issue((i + 2) % 3, (i + 2) * 32);
        CP_COMMIT();
        compute(i % 3);
    }

    /* ---- epilogue ---- */
    #pragma unroll
    for (int mf = 0; mf < MF; mf++) {
        #pragma unroll
        for (int nf = 0; nf < NF; nf++) {
            int row = rowBase + warpRow + mf * 16 + (lane >> 2);
            int col = colBase + warpCol + nf * 8 + (lane & 3) * 2;
            float bx = 0.f, by = 0.f;
            if (bias) { float2 bb = *(const float2*)(bias + col); bx = bb.x; by = bb.y; }
            float v0 = acc[mf][nf][0] * alpha + bx;
            float v1 = acc[mf][nf][1] * alpha + by;
            float v2 = acc[mf][nf][2] * alpha + bx;
            float v3 = acc[mf][nf][3] * alpha + by;
            if (GELU) { v0 = gelu_f(v0); v1 = gelu_f(v1); v2 = gelu_f(v2); v3 = gelu_f(v3); }
            long long o0 = coff + (long long)row * ldc + col;
            long long o1 = coff + (long long)(row + 8) * ldc + col;
            if (OUTBF) {
                bf162 h, l;
                split_pair(v0, v1, h, l);
                *(bf162*)(Chi + o0) = h; *(bf162*)(Clo + o0) = l;
                split_pair(v2, v3, h, l);
                *(bf162*)(Chi + o1) = h; *(bf162*)(Clo + o1) = l;
            } else {
                *(float2*)(C + o0) = make_float2(v0, v1);
                *(float2*)(C + o1) = make_float2(v2, v3);
            }
        }
    }
}

/* ---------------- elementwise fp32 -> bf16 hi/lo split --------------------- */
__global__ void __launch_bounds__(256) split_vec(
    const float* __restrict__ in, bf16* __restrict__ hi, bf16* __restrict__ lo)
{
    long long i = ((long long)blockIdx.x * 256 + threadIdx.x) * 4;
    float4 v = *(const float4*)(in + i);
    bf162 h0, l0, h1, l1;
    split_pair(v.x, v.y, h0, l0);
    split_pair(v.z, v.w, h1, l1);
    *(bf162*)(hi + i)     = h0; *(bf162*)(hi + i + 2) = h1;
    *(bf162*)(lo + i)     = l0; *(bf162*)(lo + i + 2) = l1;
}

/* ---------------- row softmax over 2048 -> bf16 hi/lo --------------------- */
__global__ void __launch_bounds__(256) softmax2048_bf(
    const float* __restrict__ S, bf16* __restrict__ Phi, bf16* __restrict__ Plo)
{
    __shared__ float red[8];
    const float* row = S + (long long)blockIdx.x * 2048;
    long long ob = (long long)blockIdx.x * 2048;
    int tid = threadIdx.x;
    float4 v0 = ((const float4*)row)[tid];
    float4 v1 = ((const float4*)row)[tid + 256];
    float m = fmaxf(fmaxf(fmaxf(v0.x, v0.y), fmaxf(v0.z, v0.w)),
                    fmaxf(fmaxf(v1.x, v1.y), fmaxf(v1.z, v1.w)));
    #pragma unroll
    for (int o = 16; o; o >>= 1) m = fmaxf(m, __shfl_xor_sync(0xffffffffu, m, o));
    if ((tid & 31) == 0) red[tid >> 5] = m;
    __syncthreads();
    m = fmaxf(fmaxf(fmaxf(red[0], red[1]), fmaxf(red[2], red[3])),
              fmaxf(fmaxf(red[4], red[5]), fmaxf(red[6], red[7])));
    v0.x = __expf(v0.x - m); v0.y = __expf(v0.y - m); v0.z = __expf(v0.z - m); v0.w = __expf(v0.w - m);
    v1.x = __expf(v1.x - m); v1.y = __expf(v1.y - m); v1.z = __expf(v1.z - m); v1.w = __expf(v1.w - m);
    float s = v0.x + v0.y + v0.z + v0.w + v1.x + v1.y + v1.z + v1.w;
    #pragma unroll
    for (int o = 16; o; o >>= 1) s += __shfl_xor_sync(0xffffffffu, s, o);
    __syncthreads();
    if ((tid & 31) == 0) red[tid >> 5] = s;
    __syncthreads();
    s = red[0] + red[1] + red[2] + red[3] + red[4] + red[5] + red[6] + red[7];
    float r = 1.0f / s;
    v0.x *= r; v0.y *= r; v0.z *= r; v0.w *= r;
    v1.x *= r; v1.y *= r; v1.z *= r; v1.w *= r;
    bf162 h0, l0, h1, l1;
    split_pair(v0.x, v0.y, h0, l0); split_pair(v0.z, v0.w, h1, l1);
    *(bf162*)(Phi + ob + tid*4)     = h0; *(bf162*)(Phi + ob + tid*4 + 2) = h1;
    *(bf162*)(Plo + ob + tid*4)     = l0; *(bf162*)(Plo + ob + tid*4 + 2) = l1;
    split_pair(v1.x, v1.y, h0, l0); split_pair(v1.z, v1.w, h1, l1);
    *(bf162*)(Phi + ob + 1024 + tid*4)     = h0; *(bf162*)(Phi + ob + 1024 + tid*4 + 2) = h1;
    *(bf162*)(Plo + ob + 1024 + tid*4)     = l0; *(bf162*)(Plo + ob + 1024 + tid*4 + 2) = l1;
}

/* ---------------- theta + softmax -> bf16 hi/lo --------------------------- */
__global__ void __launch_bounds__(256) theta_softmax2048_bf(
    const float* __restrict__ S, bf16* __restrict__ Phi, bf16* __restrict__ Plo)
{
    __shared__ float red[8];
    const float* row = S + (long long)blockIdx.x * 2048;
    long long ob = (long long)blockIdx.x * 2048;
    int tid = threadIdx.x;
    float4 v0 = ((const float4*)row)[tid];
    float4 v1 = ((const float4*)row)[tid + 256];
    v0.x = theta_fn(v0.x); v0.y = theta_fn(v0.y); v0.z = theta_fn(v0.z); v0.w = theta_fn(v0.w);
    v1.x = theta_fn(v1.x); v1.y = theta_fn(v1.y); v1.z = theta_fn(v1.z); v1.w = theta_fn(v1.w);
    float m = fmaxf(fmaxf(fmaxf(v0.x, v0.y), fmaxf(v0.z, v0.w)),
                    fmaxf(fmaxf(v1.x, v1.y), fmaxf(v1.z, v1.w)));
    #pragma unroll
    for (int o = 16; o; o >>= 1) m = fmaxf(m, __shfl_xor_sync(0xffffffffu, m, o));
    if ((tid & 31) == 0) red[tid >> 5] = m;
    __syncthreads();
    m = fmaxf(fmaxf(fmaxf(red[0], red[1]), fmaxf(red[2], red[3])),
              fmaxf(fmaxf(red[4], red[5]), fmaxf(red[6], red[7])));
    v0.x = __expf(v0.x - m); v0.y = __expf(v0.y - m); v0.z = __expf(v0.z - m); v0.w = __expf(v0.w - m);
    v1.x = __expf(v1.x - m); v1.y = __expf(v1.y - m); v1.z = __expf(v1.z - m); v1.w = __expf(v1.w - m);
    float s = v0.x + v0.y + v0.z + v0.w + v1.x + v1.y + v1.z + v1.w;
    #pragma unroll
    for (int o = 16; o; o >>= 1) s += __shfl_xor_sync(0xffffffffu, s, o);
    __syncthreads();
    if ((tid & 31) == 0) red[tid >> 5] = s;
    __syncthreads();
    s = red[0] + red[1] + red[2] + red[3] + red[4] + red[5] + red[6] + red[7];
    float r = 1.0f / s;
    v0.x *= r; v0.y *= r; v0.z *= r; v0.w *= r;
    v1.x *= r; v1.y *= r; v1.z *= r; v1.w *= r;
    bf162 h0, l0, h1, l1;
    split_pair(v0.x, v0.y, h0, l0); split_pair(v0.z, v0.w, h1, l1);
    *(bf162*)(Phi + ob + tid*4)     = h0; *(bf162*)(Phi + ob + tid*4 + 2) = h1;
    *(bf162*)(Plo + ob + tid*4)     = l0; *(bf162*)(Plo + ob + tid*4 + 2) = l1;
    split_pair(v1.x, v1.y, h0, l0); split_pair(v1.z, v1.w, h1, l1);
    *(bf162*)(Phi + ob + 1024 + tid*4)     = h0; *(bf162*)(Phi + ob + 1024 + tid*4 + 2) = h1;
    *(bf162*)(Plo + ob + 1024 + tid*4)     = l0; *(bf162*)(Plo + ob + 1024 + tid*4 + 2) = l1;
}

/* ---------------- LayerNorm over 1024 -> bf16 hi/lo ----------------------- */
__global__ void __launch_bounds__(256) layernorm1024_bf(
    const float* __restrict__ X, const float* __restrict__ g,
    const float* __restrict__ bta, bf16* __restrict__ Yhi, bf16* __restrict__ Ylo)
{
    __shared__ float rs[8], rq[8];
    long long base = (long long)blockIdx.x * 1024;
    int tid = threadIdx.x;
    float4 v = *(const float4*)(X + base + tid * 4);
    float s = v.x + v.y + v.z + v.w;
    float q = v.x*v.x + v.y*v.y + v.z*v.z + v.w*v.w;
    #pragma unroll
    for (int o = 16; o; o >>= 1) {
        s += __shfl_xor_sync(0xffffffffu, s, o);
        q += __shfl_xor_sync(0xffffffffu, q, o);
    }
    if ((tid & 31) == 0) { rs[tid >> 5] = s; rq[tid >> 5] = q; }
    __syncthreads();
    s = rs[0] + rs[1] + rs[2] + rs[3] + rs[4] + rs[5] + rs[6] + rs[7];
    q = rq[0] + rq[1] + rq[2] + rq[3] + rq[4] + rq[5] + rq[6] + rq[7];
    float mu  = s * (1.0f / 1024.0f);
    float var = q * (1.0f / 1024.0f) - mu * mu;
    float inv = rsqrtf(var + 1e-5f);
    float4 gg = *(const float4*)(g + tid * 4);
    float4 bb = *(const float4*)(bta + tid * 4);
    float o0 = (v.x - mu) * inv * gg.x + bb.x;
    float o1 = (v.y - mu) * inv * gg.y + bb.y;
    float o2 = (v.z - mu) * inv * gg.z + bb.z;
    float o3 = (v.w - mu) * inv * gg.w + bb.w;
    bf162 h0, l0, h1, l1;
    split_pair(o0, o1, h0, l0);
    split_pair(o2, o3, h1, l1);
    *(bf162*)(Yhi + base + tid*4)     = h0; *(bf162*)(Yhi + base + tid*4 + 2) = h1;
    *(bf162*)(Ylo + base + tid*4)     = l0; *(bf162*)(Ylo + base + tid*4 + 2) = l1;
}

/* ---------------- residual adds ------------------------------------------- */
__global__ void __launch_bounds__(256) add_bf(
    float* __restrict__ out, const float* __restrict__ a, const float* __restrict__ b,
    bf16* __restrict__ hi, bf16* __restrict__ lo)
{
    long long i = ((long long)blockIdx.x * 256 + threadIdx.x) * 4;
    float4 av = *(const float4*)(a + i);
    float4 bv = *(const float4*)(b + i);
    av.x += bv.x; av.y += bv.y; av.z += bv.z; av.w += bv.w;
    *(float4*)(out + i) = av;
    bf162 h0, l0, h1, l1;
    split_pair(av.x, av.y, h0, l0);
    split_pair(av.z, av.w, h1, l1);
    *(bf162*)(hi + i)     = h0; *(bf162*)(hi + i + 2) = h1;
    *(bf162*)(lo + i)     = l0; *(bf162*)(lo + i + 2) = l1;
}
__global__ void __launch_bounds__(256) add_plain(
    float* __restrict__ out, const float* __restrict__ b)
{
    long long i = ((long long)blockIdx.x * 256 + threadIdx.x) * 4;
    float4 av = *(const float4*)(out + i);
    float4 bv = *(const float4*)(b + i);
    av.x += bv.x; av.y += bv.y; av.z += bv.z; av.w += bv.w;
    *(float4*)(out + i) = av;
}

/* ---------------- host-side dispatch -------------------------------------- */
#define SMEM128 99328   /* 3*32768 + 1024 */
#define SMEM64  74752   /* 3*24576 + 1024 */

extern "C" void kernel_launch(void* const* d_in, const int* in_sizes, int n_in,
                              void* d_out, int out_size)
{
    const float* x     = (const float*)d_in[0];
    const float* ln1_g = (const float*)d_in[1];
    const float* ln1_b = (const float*)d_in[2];
    const float* qkv_w = (const float*)d_in[3];
    const float* qkv_b = (const float*)d_in[4];
    const float* proj_w= (const float*)d_in[5];
    const float* proj_b= (const float*)d_in[6];
    const float* kq_w  = (const float*)d_in[7];
    const float* kq_b  = (const float*)d_in[8];
    const float* kk_w  = (const float*)d_in[9];
    const float* kk_b  = (const float*)d_in[10];
    const float* kv_w  = (const float*)d_in[11];
    const float* kv_b  = (const float*)d_in[12];
    const float* ko_w  = (const float*)d_in[13];
    const float* ko_b  = (const float*)d_in[14];
    const float* ln2_g = (const float*)d_in[15];
    const float* ln2_b = (const float*)d_in[16];
    const float* fc1_w = (const float*)d_in[17];
    const float* fc1_b = (const float*)d_in[18];
    const float* fc2_w = (const float*)d_in[19];
    const float* fc2_b = (const float*)d_in[20];
    float* out = (float*)d_out;

    float *sc, *bufA;
    bf16 *whi, *wlo, *lnhi, *lnlo, *qkvhi, *qkvlo, *schi, *sclo;
    bf16 *aohi, *aolo, *reshi, *reslo, *ffhi, *fflo;
    cudaGetSymbolAddress((void**)&sc,    g_sc);
    cudaGetSymbolAddress((void**)&bufA,  g_bufA);
    cudaGetSymbolAddress((void**)&whi,   g_whi);
    cudaGetSymbolAddress((void**)&wlo,   g_wlo);
    cudaGetSymbolAddress((void**)&lnhi,  g_lnhi);
    cudaGetSymbolAddress((void**)&lnlo,  g_lnlo);
    cudaGetSymbolAddress((void**)&qkvhi, g_qkvhi);
    cudaGetSymbolAddress((void**)&qkvlo, g_qkvlo);
    cudaGetSymbolAddress((void**)&schi,  g_schi);
    cudaGetSymbolAddress((void**)&sclo,  g_sclo);
    cudaGetSymbolAddress((void**)&aohi,  g_aohi);
    cudaGetSymbolAddress((void**)&aolo,  g_aolo);
    cudaGetSymbolAddress((void**)&reshi, g_reshi);
    cudaGetSymbolAddress((void**)&reslo, g_reslo);
    cudaGetSymbolAddress((void**)&ffhi,  g_ffhi);
    cudaGetSymbolAddress((void**)&fflo,  g_fflo);

    cudaFuncSetAttribute(bgemm<128, false, false, true >, cudaFuncAttributeMaxDynamicSharedMemorySize, SMEM128);
    cudaFuncSetAttribute(bgemm<128, false, false, false>, cudaFuncAttributeMaxDynamicSharedMemorySize, SMEM128);
    cudaFuncSetAttribute(bgemm<128, false, true,  true >, cudaFuncAttributeMaxDynamicSharedMemorySize, SMEM128);
    cudaFuncSetAttribute(bgemm<128, true,  false, false>, cudaFuncAttributeMaxDynamicSharedMemorySize, SMEM128);
    cudaFuncSetAttribute(bgemm<64,  false, false, true >, cudaFuncAttributeMaxDynamicSharedMemorySize, SMEM64);

    const long long NN = (long long)NTOK * NTOK;
    const long long TC = (long long)NTOK * DIMC;
    const int nElemBlks = (TTOK * DIMC) / (4 * 256);
    dim3 tb(256);

    /* ---- weight splits (elementwise, same layout) ---- */
    split_vec<<<3072, tb>>>(qkv_w,  whi + W_QKV,  wlo + W_QKV);
    split_vec<<<1024, tb>>>(proj_w, whi + W_PROJ, wlo + W_PROJ);
    split_vec<<<1024, tb>>>(kq_w,   whi + W_KQ,   wlo + W_KQ);
    split_vec<<<1024, tb>>>(kk_w,   whi + W_KK,   wlo + W_KK);
    split_vec<<<1024, tb>>>(kv_w,   whi + W_KV,   wlo + W_KV);
    split_vec<<<1024, tb>>>(ko_w,   whi + W_KO,   wlo + W_KO);
    split_vec<<<4096, tb>>>(fc1_w,  whi + W_FC1,  wlo + W_FC1);
    split_vec<<<4096, tb>>>(fc2_w,  whi + W_FC2,  wlo + W_FC2);

    /* ---- sublayer 1: MHA ---- */
    layernorm1024_bf<<<TTOK, tb>>>(x, ln1_g, ln1_b, lnhi, lnlo);

    /* qkv = ln1 @ qkv_w + b -> bf16 [4096, 3072] */
    bgemm<128, false, false, true><<<dim3(24, 32, 1), tb, SMEM128>>>(
        lnhi, lnlo, whi + W_QKV, wlo + W_QKV, nullptr, qkvhi, qkvlo, qkv_b,
        1024, 1024, 3072, 3072, 1, 0,0, 0,0, 0,0, 1.0f);

    /* scores = q @ k^T * scale ; z = b*16+h */
    bgemm<128, true, false, false><<<dim3(16, 16, BATCHN*NHEADS), tb, SMEM128>>>(
        qkvhi, qkvlo, qkvhi + DIMC, qkvlo + DIMC, sc, nullptr, nullptr, nullptr,
        64, 3*DIMC, 3*DIMC, NTOK, NHEADS,
        (long long)NTOK*3*DIMC, HDIM, (long long)NTOK*3*DIMC, HDIM,
        (long long)NHEADS*NN, NN, 0.125f);

    softmax2048_bf<<<BATCHN*NHEADS*NTOK, tb>>>(sc, schi, sclo);

    /* out_heads = attn @ v -> bf16 [4096, 1024] (NN on v, no transpose) */
    bgemm<64, false, false, true><<<dim3(1, 16, BATCHN*NHEADS), tb, SMEM64>>>(
        schi, sclo, qkvhi + 2*DIMC, qkvlo + 2*DIMC, nullptr, aohi, aolo, nullptr,
        NTOK, NTOK, 3*DIMC, DIMC, NHEADS,
        (long long)NHEADS*NN, NN, (long long)NTOK*3*DIMC, HDIM,
        TC, HDIM, 1.0f);

    bgemm<128, false, false, false><<<dim3(8, 32, 1), tb, SMEM128>>>(
        aohi, aolo, whi + W_PROJ, wlo + W_PROJ, bufA, nullptr, nullptr, proj_b,
        1024, 1024, 1024, 1024, 1, 0,0, 0,0, 0,0, 1.0f);
    add_bf<<<nElemBlks, tb>>>(out, x, bufA, reshi, reslo);

    /* ---- sublayer 2: kernel attention ---- */
    bf16* bqhi = qkvhi;                 bf16* bqlo = qkvlo;
    bf16* bkhi = qkvhi + (size_t)TTOK*DIMC;   bf16* bklo = qkvlo + (size_t)TTOK*DIMC;
    bf16* bvhi = qkvhi + (size_t)2*TTOK*DIMC; bf16* bvlo = qkvlo + (size_t)2*TTOK*DIMC;

    bgemm<128, false, false, true><<<dim3(8, 32, 1), tb, SMEM128>>>(
        reshi, reslo, whi + W_KQ, wlo + W_KQ, nullptr, bqhi, bqlo, kq_b,
        1024, 1024, 1024, 1024, 1, 0,0, 0,0, 0,0, 1.0f);
    bgemm<128, false, false, true><<<dim3(8, 32, 1), tb, SMEM128>>>(
        reshi, reslo, whi + W_KK, wlo + W_KK, nullptr, bkhi, bklo, kk_b,
        1024, 1024, 1024, 1024, 1, 0,0, 0,0, 0,0, 1.0f);
    bgemm<128, false, false, true><<<dim3(8, 32, 1), tb, SMEM128>>>(
        reshi, reslo, whi + W_KV, wlo + W_KV, nullptr, bvhi, bvlo, kv_b,
        1024, 1024, 1024, 1024, 1, 0,0, 0,0, 0,0, 1.0f);

    /* qk = q @ k^T per batch (K=1024) */
    bgemm<128, true, false, false><<<dim3(16, 16, BATCHN), tb, SMEM128>>>(
        bqhi, bqlo, bkhi, bklo, sc, nullptr, nullptr, nullptr,
        1024, 1024, 1024, NTOK, 1, TC, 0, TC, 0, NN, 0, 1.0f);

    theta_softmax2048_bf<<<BATCHN*NTOK, tb>>>(sc, schi, sclo);

    /* av = attn @ v per batch (NN) */
    bgemm<128, false, false, true><<<dim3(8, 16, BATCHN), tb, SMEM128>>>(
        schi, sclo, bvhi, bvlo, nullptr, aohi, aolo, nullptr,
        NTOK, NTOK, DIMC, DIMC, 1, NN, 0, TC, 0, TC, 0, 1.0f);

    bgemm<128, false, false, false><<<dim3(8, 32, 1), tb, SMEM128>>>(
        aohi, aolo, whi + W_KO, wlo + W_KO, bufA, nullptr, nullptr, ko_b,
        1024, 1024, 1024, 1024, 1, 0,0, 0,0, 0,0, 1.0f);
    add_plain<<<nElemBlks, tb>>>(out, bufA);

    /* ---- sublayer 3: FFN ---- */
    layernorm1024_bf<<<TTOK, tb>>>(out, ln2_g, ln2_b, lnhi, lnlo);
    bgemm<128, false, true, true><<<dim3(32, 32, 1), tb, SMEM128>>>(
        lnhi, lnlo, whi + W_FC1, wlo + W_FC1, nullptr, ffhi, fflo, fc1_b,
        1024, 1024, 4096, 4096, 1, 0,0, 0,0, 0,0, 1.0f);
    bgemm<128, false, false, false><<<dim3(8, 32, 1), tb, SMEM128>>>(
        ffhi, fflo, whi + W_FC2, wlo + W_FC2, bufA, nullptr, nullptr, fc2_b,
        4096, 4096, 1024, 1024, 1, 0,0, 0,0, 0,0, 1.0f);
    add_plain<<<nElemBlks, tb>>>(out, bufA);
}